// round 13
// baseline (speedup 1.0000x reference)
#include <cuda_runtime.h>
#include <math.h>

#define DIMC    256
#define NHEAD   4
#define HDIM    64
#define VV      3
#define BB      2
#define NN      1024
#define LL      3072           // VV*NN
#define MROWS   6144           // BB*LL
#define SCALE_F 0.125f         // 64^-0.5 (exact power of two)
#define LNEPS   1e-5f

// ---------------- scratch ----------------
__device__ float g_x[MROWS*DIMC];
__device__ float g_q[MROWS*DIMC];
__device__ float g_k[MROWS*DIMC];
__device__ float g_v[MROWS*DIMC];
__device__ float g_o[MROWS*DIMC];
__device__ float g_p[MROWS*DIMC];

__device__ __forceinline__ float to_tf32(float x){
    asm("cvt.rna.tf32.f32 %0, %0;" : "+f"(x));
    return x;
}
__device__ __forceinline__ void mma8(float c[4],
                                     unsigned a0, unsigned a1, unsigned a2, unsigned a3,
                                     unsigned b0, unsigned b1){
    asm volatile("mma.sync.aligned.m16n8k8.row.col.f32.tf32.tf32.f32 "
        "{%0,%1,%2,%3},{%4,%5,%6,%7},{%8,%9},{%0,%1,%2,%3};"
        : "+f"(c[0]),"+f"(c[1]),"+f"(c[2]),"+f"(c[3])
        : "r"(a0),"r"(a1),"r"(a2),"r"(a3),"r"(b0),"r"(b1));
}

// ---------------- 1) pack features (V,B,C,N) -> x[B, L, C], tf32-rounded ----------------
__global__ void pack_x(const float* __restrict__ f) {
    __shared__ float tile[32][33];
    int vb = blockIdx.z;
    int v  = vb / BB, b = vb % BB;
    int n0 = blockIdx.x * 32, c0 = blockIdx.y * 32;
    int tx = threadIdx.x, ty = threadIdx.y;
    tile[ty][tx] = f[((size_t)vb*DIMC + (c0+ty))*NN + n0 + tx];
    __syncthreads();
    g_x[((size_t)(b*LL + v*NN + n0 + ty))*DIMC + c0 + tx] = to_tf32(tile[tx][ty]);
}

// ---------------- 2) fused QKV GEMM (tf32 mma) ----------------
// BM=64, BN=128, BK=32; 256 threads; warp grid 2x4; warp tile 32x32
__global__ void gemm_qkv(const float* __restrict__ A,
                         const float* __restrict__ Wq, const float* __restrict__ bq,
                         const float* __restrict__ Wk, const float* __restrict__ bk,
                         const float* __restrict__ Wv, const float* __restrict__ bv) {
    const float* W; const float* bias; float* C;
    if (blockIdx.z == 0)      { W = Wq; bias = bq; C = g_q; }
    else if (blockIdx.z == 1) { W = Wk; bias = bk; C = g_k; }
    else                      { W = Wv; bias = bv; C = g_v; }

    __shared__ float As[64][36];
    __shared__ float Ws[128][36];
    int tid = threadIdx.x;
    int warp = tid >> 5, lane = tid & 31;
    int group = lane >> 2, tig = lane & 3;
    int wm = warp >> 2, wn = warp & 3;
    int m0 = blockIdx.x * 64, n0 = blockIdx.y * 128;

    float acc[2][4][4];
#pragma unroll
    for (int mi = 0; mi < 2; mi++)
#pragma unroll
        for (int nj = 0; nj < 4; nj++)
#pragma unroll
            for (int c = 0; c < 4; c++) acc[mi][nj][c] = 0.f;

    for (int kk = 0; kk < 256; kk += 32) {
#pragma unroll
        for (int i = 0; i < 2; i++) {
            int p = tid + 256*i;
            int r = p >> 3, c4 = (p & 7) * 4;
            float4 a4 = *(const float4*)&A[(size_t)(m0+r)*256 + kk + c4];
            As[r][c4+0]=a4.x; As[r][c4+1]=a4.y; As[r][c4+2]=a4.z; As[r][c4+3]=a4.w;
        }
#pragma unroll
        for (int i = 0; i < 4; i++) {
            int p = tid + 256*i;
            int r = p >> 3, c4 = (p & 7) * 4;
            float4 w4 = *(const float4*)&W[(size_t)(n0+r)*256 + kk + c4];
            Ws[r][c4+0]=to_tf32(w4.x); Ws[r][c4+1]=to_tf32(w4.y);
            Ws[r][c4+2]=to_tf32(w4.z); Ws[r][c4+3]=to_tf32(w4.w);
        }
        __syncthreads();
#pragma unroll
        for (int ks = 0; ks < 4; ks++) {
            unsigned a[2][4], b[4][2];
#pragma unroll
            for (int mi = 0; mi < 2; mi++) {
                int mr = wm*32 + mi*16 + group;
                a[mi][0] = __float_as_uint(As[mr  ][ks*8+tig  ]);
                a[mi][1] = __float_as_uint(As[mr+8][ks*8+tig  ]);
                a[mi][2] = __float_as_uint(As[mr  ][ks*8+tig+4]);
                a[mi][3] = __float_as_uint(As[mr+8][ks*8+tig+4]);
            }
#pragma unroll
            for (int nj = 0; nj < 4; nj++) {
                int nr = wn*32 + nj*8 + group;
                b[nj][0] = __float_as_uint(Ws[nr][ks*8+tig  ]);
                b[nj][1] = __float_as_uint(Ws[nr][ks*8+tig+4]);
            }
#pragma unroll
            for (int mi = 0; mi < 2; mi++)
#pragma unroll
                for (int nj = 0; nj < 4; nj++)
                    mma8(acc[mi][nj], a[mi][0],a[mi][1],a[mi][2],a[mi][3], b[nj][0],b[nj][1]);
        }
        __syncthreads();
    }
#pragma unroll
    for (int mi = 0; mi < 2; mi++) {
        int r0 = m0 + wm*32 + mi*16 + group;
#pragma unroll
        for (int nj = 0; nj < 4; nj++) {
            int c = n0 + wn*32 + nj*8 + 2*tig;
            float b0v = bias[c], b1v = bias[c+1];
            float2 v0 = make_float2(to_tf32(acc[mi][nj][0]+b0v), to_tf32(acc[mi][nj][1]+b1v));
            float2 v1 = make_float2(to_tf32(acc[mi][nj][2]+b0v), to_tf32(acc[mi][nj][3]+b1v));
            *(float2*)&C[(size_t)r0*256 + c]     = v0;
            *(float2*)&C[(size_t)(r0+8)*256 + c] = v1;
        }
    }
}

// ---------------- 3) flash attention, tf32 mma, 128 queries/block, warp tile M=32 ----------------
// dynamic smem: Qs[128][68] | Kt[64][68] | Vs[64][72] | Ps[128][68]
#define QS_OFF 0
#define KT_OFF (128*68)
#define VS_OFF (KT_OFF + 64*68)
#define PS_OFF (VS_OFF + 64*72)
#define ATTN_SMEM ((PS_OFF + 128*68)*4)

__global__ void __launch_bounds__(128) attn_mma(const float* __restrict__ Q,
                         const float* __restrict__ K,
                         const float* __restrict__ V,
                         float* __restrict__ O) {
    extern __shared__ float sm[];
    float* Qs = sm + QS_OFF;
    float* Kt = sm + KT_OFF;
    float* Vs = sm + VS_OFF;
    float* Ps = sm + PS_OFF;

    int tid  = threadIdx.x;
    int warp = tid >> 5, lane = tid & 31;
    int group = lane >> 2, tig = lane & 3;
    int q0 = blockIdx.x * 128;
    int h  = blockIdx.y, b = blockIdx.z;
    const size_t base = ((size_t)b * LL) * DIMC + (size_t)h * HDIM;

    // load Q tile, fold SCALE (exact pow2, preserves tf32 rounding)
#pragma unroll
    for (int i = 0; i < 16; i++) {
        int p = tid + 128*i;
        int r = p >> 4, c4 = (p & 15) * 4;
        float4 q4 = *(const float4*)&Q[base + (size_t)(q0+r)*256 + c4];
        float* dst = &Qs[r*68 + c4];
        dst[0] = q4.x*SCALE_F; dst[1] = q4.y*SCALE_F;
        dst[2] = q4.z*SCALE_F; dst[3] = q4.w*SCALE_F;
    }
    __syncthreads();

    float mst[2][2], lst[2][2];
#pragma unroll
    for (int mi = 0; mi < 2; mi++) { mst[mi][0]=mst[mi][1]=-1e30f; lst[mi][0]=lst[mi][1]=0.f; }
    float o[2][8][4];
#pragma unroll
    for (int mi = 0; mi < 2; mi++)
#pragma unroll
        for (int nj = 0; nj < 8; nj++)
#pragma unroll
            for (int c = 0; c < 4; c++) o[mi][nj][c] = 0.f;

    int rbase = warp*32 + group;

    for (int kt = 0; kt < LL; kt += 64) {
#pragma unroll
        for (int i = 0; i < 8; i++) {
            int p = tid + 128*i;
            int r = p >> 4, c4 = (p & 15) * 4;
            *(float4*)&Kt[r*68 + c4] = *(const float4*)&K[base + (size_t)(kt+r)*256 + c4];
            *(float4*)&Vs[r*72 + c4] = *(const float4*)&V[base + (size_t)(kt+r)*256 + c4];
        }
        __syncthreads();

        // S = (Q*scale) Kt
        float s[2][8][4];
#pragma unroll
        for (int mi = 0; mi < 2; mi++)
#pragma unroll
            for (int nj = 0; nj < 8; nj++)
#pragma unroll
                for (int c = 0; c < 4; c++) s[mi][nj][c] = 0.f;
#pragma unroll
        for (int ks = 0; ks < 8; ks++) {
            unsigned a[2][4];
#pragma unroll
            for (int mi = 0; mi < 2; mi++) {
                const float* qp = &Qs[(rbase + mi*16)*68 + ks*8];
                a[mi][0] = __float_as_uint(qp[tig]);
                a[mi][1] = __float_as_uint(qp[8*68 + tig]);
                a[mi][2] = __float_as_uint(qp[tig+4]);
                a[mi][3] = __float_as_uint(qp[8*68 + tig+4]);
            }
#pragma unroll
            for (int nj = 0; nj < 8; nj++) {
                const float* kp = &Kt[(nj*8+group)*68 + ks*8];
                unsigned b0 = __float_as_uint(kp[tig]);
                unsigned b1 = __float_as_uint(kp[tig+4]);
                mma8(s[0][nj], a[0][0],a[0][1],a[0][2],a[0][3], b0,b1);
                mma8(s[1][nj], a[1][0],a[1][1],a[1][2],a[1][3], b0,b1);
            }
        }

        // online softmax: 4 rows/thread, quad-shuffle reductions
#pragma unroll
        for (int mi = 0; mi < 2; mi++)
#pragma unroll
            for (int hf = 0; hf < 2; hf++) {
                float mx = -1e30f;
#pragma unroll
                for (int nj = 0; nj < 8; nj++)
                    mx = fmaxf(mx, fmaxf(s[mi][nj][2*hf], s[mi][nj][2*hf+1]));
                mx = fmaxf(mx, __shfl_xor_sync(0xffffffffu, mx, 1));
                mx = fmaxf(mx, __shfl_xor_sync(0xffffffffu, mx, 2));
                float mn = fmaxf(mst[mi][hf], mx);
                float sum = 0.f;
#pragma unroll
                for (int nj = 0; nj < 8; nj++) {
                    float e0 = __expf(s[mi][nj][2*hf]   - mn);
                    float e1 = __expf(s[mi][nj][2*hf+1] - mn);
                    s[mi][nj][2*hf] = e0; s[mi][nj][2*hf+1] = e1;
                    sum += e0 + e1;
                }
                sum += __shfl_xor_sync(0xffffffffu, sum, 1);
                sum += __shfl_xor_sync(0xffffffffu, sum, 2);
                float alpha = __expf(mst[mi][hf] - mn);
                lst[mi][hf] = lst[mi][hf]*alpha + sum;
                mst[mi][hf] = mn;
#pragma unroll
                for (int nj = 0; nj < 8; nj++) {
                    o[mi][nj][2*hf]   *= alpha;
                    o[mi][nj][2*hf+1] *= alpha;
                }
            }

        // store P (warp-private rows) tf32-rounded
#pragma unroll
        for (int mi = 0; mi < 2; mi++) {
            int r0 = rbase + mi*16;
#pragma unroll
            for (int nj = 0; nj < 8; nj++) {
                int c = nj*8 + 2*tig;
                *(float2*)&Ps[r0*68 + c]     = make_float2(to_tf32(s[mi][nj][0]), to_tf32(s[mi][nj][1]));
                *(float2*)&Ps[(r0+8)*68 + c] = make_float2(to_tf32(s[mi][nj][2]), to_tf32(s[mi][nj][3]));
            }
        }
        __syncwarp();

        // O += P V
#pragma unroll
        for (int ks = 0; ks < 8; ks++) {
            unsigned a[2][4];
#pragma unroll
            for (int mi = 0; mi < 2; mi++) {
                const float* pp = &Ps[(rbase + mi*16)*68 + ks*8];
                a[mi][0] = __float_as_uint(pp[tig]);
                a[mi][1] = __float_as_uint(pp[8*68 + tig]);
                a[mi][2] = __float_as_uint(pp[tig+4]);
                a[mi][3] = __float_as_uint(pp[8*68 + tig+4]);
            }
#pragma unroll
            for (int nj = 0; nj < 8; nj++) {
                unsigned b0 = __float_as_uint(Vs[(ks*8+tig)*72 + nj*8+group]);
                unsigned b1 = __float_as_uint(Vs[(ks*8+tig+4)*72 + nj*8+group]);
                mma8(o[0][nj], a[0][0],a[0][1],a[0][2],a[0][3], b0,b1);
                mma8(o[1][nj], a[1][0],a[1][1],a[1][2],a[1][3], b0,b1);
            }
        }
        __syncthreads();      // before next tile overwrites Kt/Vs
    }

#pragma unroll
    for (int mi = 0; mi < 2; mi++)
#pragma unroll
        for (int hf = 0; hf < 2; hf++) {
            float inv = 1.f / lst[mi][hf];
            size_t r = q0 + rbase + mi*16 + hf*8;
#pragma unroll
            for (int nj = 0; nj < 8; nj++) {
                int c = nj*8 + 2*tig;
                *(float2*)&O[base + r*256 + c] =
                    make_float2(to_tf32(o[mi][nj][2*hf]*inv), to_tf32(o[mi][nj][2*hf+1]*inv));
            }
        }
}

// ---------------- 4) output projection (tf32 mma) + fused LayerNorm ----------------
// BM=32, BN=256; 256 threads; warp grid 2(m)x4(n); warp tile 16x64; grid 192
__global__ void gemm_p_ln(const float* __restrict__ A, const float* __restrict__ W,
                          const float* __restrict__ bias, const float* __restrict__ gamma,
                          const float* __restrict__ beta, float* __restrict__ Out) {
    __shared__ float As[32][36];
    __shared__ float Ws[256][36];
    __shared__ float psum[32][4];
    __shared__ float psq[32][4];
    int tid = threadIdx.x;
    int warp = tid >> 5, lane = tid & 31;
    int group = lane >> 2, tig = lane & 3;
    int wm = warp >> 2, wn = warp & 3;
    int m0 = blockIdx.x * 32;

    float acc[8][4];
#pragma unroll
    for (int nj = 0; nj < 8; nj++)
#pragma unroll
        for (int c = 0; c < 4; c++) acc[nj][c] = 0.f;

    for (int kk = 0; kk < 256; kk += 32) {
        {
            int r = tid >> 3, c4 = (tid & 7) * 4;
            float4 a4 = *(const float4*)&A[(size_t)(m0+r)*256 + kk + c4];
            As[r][c4+0]=a4.x; As[r][c4+1]=a4.y; As[r][c4+2]=a4.z; As[r][c4+3]=a4.w;
        }
#pragma unroll
        for (int i = 0; i < 8; i++) {
            int p = tid + 256*i;
            int r = p >> 3, c4 = (p & 7) * 4;
            float4 w4 = *(const float4*)&W[(size_t)r*256 + kk + c4];
            Ws[r][c4+0]=to_tf32(w4.x); Ws[r][c4+1]=to_tf32(w4.y);
            Ws[r][c4+2]=to_tf32(w4.z); Ws[r][c4+3]=to_tf32(w4.w);
        }
        __syncthreads();
#pragma unroll
        for (int ks = 0; ks < 4; ks++) {
            unsigned a0,a1,a2,a3;
            int mr = wm*16 + group;
            a0 = __float_as_uint(As[mr  ][ks*8+tig  ]);
            a1 = __float_as_uint(As[mr+8][ks*8+tig  ]);
            a2 = __float_as_uint(As[mr  ][ks*8+tig+4]);
            a3 = __float_as_uint(As[mr+8][ks*8+tig+4]);
#pragma unroll
            for (int nj = 0; nj < 8; nj++) {
                int nr = wn*64 + nj*8 + group;
                unsigned b0 = __float_as_uint(Ws[nr][ks*8+tig  ]);
                unsigned b1 = __float_as_uint(Ws[nr][ks*8+tig+4]);
                mma8(acc[nj], a0,a1,a2,a3, b0,b1);
            }
        }
        __syncthreads();
    }

    // bias + per-row partial stats over this warp's 64 columns
    float rs[2] = {0.f, 0.f}, rq[2] = {0.f, 0.f};
#pragma unroll
    for (int nj = 0; nj < 8; nj++) {
        int c = wn*64 + nj*8 + 2*tig;
        float b0v = bias[c], b1v = bias[c+1];
        acc[nj][0] += b0v; acc[nj][1] += b1v;
        acc[nj][2] += b0v; acc[nj][3] += b1v;
        rs[0] += acc[nj][0] + acc[nj][1];
        rq[0] += acc[nj][0]*acc[nj][0] + acc[nj][1]*acc[nj][1];
        rs[1] += acc[nj][2] + acc[nj][3];
        rq[1] += acc[nj][2]*acc[nj][2] + acc[nj][3]*acc[nj][3];
    }
#pragma unroll
    for (int hf = 0; hf < 2; hf++) {
        rs[hf] += __shfl_xor_sync(0xffffffffu, rs[hf], 1);
        rs[hf] += __shfl_xor_sync(0xffffffffu, rs[hf], 2);
        rq[hf] += __shfl_xor_sync(0xffffffffu, rq[hf], 1);
        rq[hf] += __shfl_xor_sync(0xffffffffu, rq[hf], 2);
    }
    if (tig == 0) {
        int lr = wm*16 + group;
        psum[lr][wn]   = rs[0];  psq[lr][wn]   = rq[0];
        psum[lr+8][wn] = rs[1];  psq[lr+8][wn] = rq[1];
    }
    __syncthreads();
#pragma unroll
    for (int hf = 0; hf < 2; hf++) {
        int lr = wm*16 + group + hf*8;
        float S   = psum[lr][0] + psum[lr][1] + psum[lr][2] + psum[lr][3];
        float Qs2 = psq[lr][0]  + psq[lr][1]  + psq[lr][2]  + psq[lr][3];
        float mu  = S * (1.f/256.f);
        float var = Qs2 * (1.f/256.f) - mu*mu;
        float rstd = rsqrtf(var + LNEPS);
        size_t r = m0 + lr;
#pragma unroll
        for (int nj = 0; nj < 8; nj++) {
            int c = wn*64 + nj*8 + 2*tig;
            float v0 = acc[nj][hf*2+0], v1 = acc[nj][hf*2+1];
            *(float2*)&Out[r*256 + c] = make_float2((v0-mu)*rstd*gamma[c]   + beta[c],
                                                    (v1-mu)*rstd*gamma[c+1] + beta[c+1]);
        }
    }
}

// ---------------- 5) mean over views + transpose to [B, C, H, W] ----------------
__global__ void mean_views(float* __restrict__ out) {
    __shared__ float tile[32][33];
    int b  = blockIdx.z;
    int n0 = blockIdx.x * 32, c0 = blockIdx.y * 32;
    int tx = threadIdx.x, ty = threadIdx.y;
    float s = 0.f;
#pragma unroll
    for (int v = 0; v < VV; v++)
        s += g_p[((size_t)(b*LL + v*NN + n0 + ty))*DIMC + c0 + tx];
    tile[ty][tx] = s * (1.0f/3.0f);
    __syncthreads();
    out[((size_t)(b*DIMC + c0 + ty))*NN + n0 + tx] = tile[tx][ty];
}

// ---------------- launch ----------------
extern "C" void kernel_launch(void* const* d_in, const int* in_sizes, int n_in,
                              void* d_out, int out_size) {
    const float* f     = (const float*)d_in[0];
    const float* Wq    = (const float*)d_in[1];
    const float* bq    = (const float*)d_in[2];
    const float* Wk    = (const float*)d_in[3];
    const float* bk    = (const float*)d_in[4];
    const float* Wv    = (const float*)d_in[5];
    const float* bv    = (const float*)d_in[6];
    const float* Wp    = (const float*)d_in[7];
    const float* bp    = (const float*)d_in[8];
    const float* gamma = (const float*)d_in[9];
    const float* beta  = (const float*)d_in[10];
    float* out = (float*)d_out;

    float *px, *pq, *pk, *pv, *po, *pp;
    cudaGetSymbolAddress((void**)&px, g_x);
    cudaGetSymbolAddress((void**)&pq, g_q);
    cudaGetSymbolAddress((void**)&pk, g_k);
    cudaGetSymbolAddress((void**)&pv, g_v);
    cudaGetSymbolAddress((void**)&po, g_o);
    cudaGetSymbolAddress((void**)&pp, g_p);

    static int smem_set = 0;
    if (!smem_set) {
        cudaFuncSetAttribute(attn_mma, cudaFuncAttributeMaxDynamicSharedMemorySize, ATTN_SMEM);
        smem_set = 1;
    }

    pack_x<<<dim3(NN/32, DIMC/32, VV*BB), dim3(32,32)>>>(f);
    gemm_qkv<<<dim3(MROWS/64, 2, 3), 256>>>(px, Wq, bq, Wk, bk, Wv, bv);
    attn_mma<<<dim3(LL/128, NHEAD, BB), 128, ATTN_SMEM>>>(pq, pk, pv, po);
    gemm_p_ln<<<MROWS/32, 256>>>(po, Wp, bp, gamma, beta, pp);
    mean_views<<<dim3(NN/32, DIMC/32, BB), dim3(32,32)>>>(out);
}

// round 14
// speedup vs baseline: 1.0050x; 1.0050x over previous
#include <cuda_runtime.h>
#include <math.h>

#define DIMC    256
#define NHEAD   4
#define HDIM    64
#define VV      3
#define BB      2
#define NN      1024
#define LL      3072           // VV*NN
#define MROWS   6144           // BB*LL
#define SCALE_F 0.125f         // 64^-0.5 (exact power of two)
#define LNEPS   1e-5f

// ---------------- scratch ----------------
__device__ float g_x[MROWS*DIMC];
__device__ float g_q[MROWS*DIMC];
__device__ float g_k[MROWS*DIMC];
__device__ float g_v[MROWS*DIMC];
__device__ float g_o[MROWS*DIMC];
__device__ float g_p[MROWS*DIMC];

__device__ __forceinline__ float to_tf32(float x){
    asm("cvt.rna.tf32.f32 %0, %0;" : "+f"(x));
    return x;
}
__device__ __forceinline__ void mma8(float c[4],
                                     unsigned a0, unsigned a1, unsigned a2, unsigned a3,
                                     unsigned b0, unsigned b1){
    asm volatile("mma.sync.aligned.m16n8k8.row.col.f32.tf32.tf32.f32 "
        "{%0,%1,%2,%3},{%4,%5,%6,%7},{%8,%9},{%0,%1,%2,%3};"
        : "+f"(c[0]),"+f"(c[1]),"+f"(c[2]),"+f"(c[3])
        : "r"(a0),"r"(a1),"r"(a2),"r"(a3),"r"(b0),"r"(b1));
}

// ---------------- 1) pack features (V,B,C,N) -> x[B, L, C], tf32-rounded ----------------
__global__ void pack_x(const float* __restrict__ f) {
    __shared__ float tile[32][33];
    int vb = blockIdx.z;
    int v  = vb / BB, b = vb % BB;
    int n0 = blockIdx.x * 32, c0 = blockIdx.y * 32;
    int tx = threadIdx.x, ty = threadIdx.y;
    tile[ty][tx] = f[((size_t)vb*DIMC + (c0+ty))*NN + n0 + tx];
    __syncthreads();
    g_x[((size_t)(b*LL + v*NN + n0 + ty))*DIMC + c0 + tx] = to_tf32(tile[tx][ty]);
}

// ---------------- 2) fused QKV GEMM (tf32 mma) ----------------
// BM=64, BN=128, BK=32; 256 threads; warp grid 2x4; warp tile 32x32
__global__ void gemm_qkv(const float* __restrict__ A,
                         const float* __restrict__ Wq, const float* __restrict__ bq,
                         const float* __restrict__ Wk, const float* __restrict__ bk,
                         const float* __restrict__ Wv, const float* __restrict__ bv) {
    const float* W; const float* bias; float* C;
    if (blockIdx.z == 0)      { W = Wq; bias = bq; C = g_q; }
    else if (blockIdx.z == 1) { W = Wk; bias = bk; C = g_k; }
    else                      { W = Wv; bias = bv; C = g_v; }

    __shared__ float As[64][36];
    __shared__ float Ws[128][36];
    int tid = threadIdx.x;
    int warp = tid >> 5, lane = tid & 31;
    int group = lane >> 2, tig = lane & 3;
    int wm = warp >> 2, wn = warp & 3;
    int m0 = blockIdx.x * 64, n0 = blockIdx.y * 128;

    float acc[2][4][4];
#pragma unroll
    for (int mi = 0; mi < 2; mi++)
#pragma unroll
        for (int nj = 0; nj < 4; nj++)
#pragma unroll
            for (int c = 0; c < 4; c++) acc[mi][nj][c] = 0.f;

    for (int kk = 0; kk < 256; kk += 32) {
#pragma unroll
        for (int i = 0; i < 2; i++) {
            int p = tid + 256*i;
            int r = p >> 3, c4 = (p & 7) * 4;
            float4 a4 = *(const float4*)&A[(size_t)(m0+r)*256 + kk + c4];
            As[r][c4+0]=a4.x; As[r][c4+1]=a4.y; As[r][c4+2]=a4.z; As[r][c4+3]=a4.w;
        }
#pragma unroll
        for (int i = 0; i < 4; i++) {
            int p = tid + 256*i;
            int r = p >> 3, c4 = (p & 7) * 4;
            float4 w4 = *(const float4*)&W[(size_t)(n0+r)*256 + kk + c4];
            Ws[r][c4+0]=to_tf32(w4.x); Ws[r][c4+1]=to_tf32(w4.y);
            Ws[r][c4+2]=to_tf32(w4.z); Ws[r][c4+3]=to_tf32(w4.w);
        }
        __syncthreads();
#pragma unroll
        for (int ks = 0; ks < 4; ks++) {
            unsigned a[2][4], b[4][2];
#pragma unroll
            for (int mi = 0; mi < 2; mi++) {
                int mr = wm*32 + mi*16 + group;
                a[mi][0] = __float_as_uint(As[mr  ][ks*8+tig  ]);
                a[mi][1] = __float_as_uint(As[mr+8][ks*8+tig  ]);
                a[mi][2] = __float_as_uint(As[mr  ][ks*8+tig+4]);
                a[mi][3] = __float_as_uint(As[mr+8][ks*8+tig+4]);
            }
#pragma unroll
            for (int nj = 0; nj < 4; nj++) {
                int nr = wn*32 + nj*8 + group;
                b[nj][0] = __float_as_uint(Ws[nr][ks*8+tig  ]);
                b[nj][1] = __float_as_uint(Ws[nr][ks*8+tig+4]);
            }
#pragma unroll
            for (int mi = 0; mi < 2; mi++)
#pragma unroll
                for (int nj = 0; nj < 4; nj++)
                    mma8(acc[mi][nj], a[mi][0],a[mi][1],a[mi][2],a[mi][3], b[nj][0],b[nj][1]);
        }
        __syncthreads();
    }
#pragma unroll
    for (int mi = 0; mi < 2; mi++) {
        int r0 = m0 + wm*32 + mi*16 + group;
#pragma unroll
        for (int nj = 0; nj < 4; nj++) {
            int c = n0 + wn*32 + nj*8 + 2*tig;
            float b0v = bias[c], b1v = bias[c+1];
            float2 v0 = make_float2(to_tf32(acc[mi][nj][0]+b0v), to_tf32(acc[mi][nj][1]+b1v));
            float2 v1 = make_float2(to_tf32(acc[mi][nj][2]+b0v), to_tf32(acc[mi][nj][3]+b1v));
            *(float2*)&C[(size_t)r0*256 + c]     = v0;
            *(float2*)&C[(size_t)(r0+8)*256 + c] = v1;
        }
    }
}

// ---------------- 3) flash attention, tf32 mma, 128 queries/block, warp tile M=32 ----------------
// dynamic smem: Qs[128][68] | Kt[64][68] | Vs[64][72] | Ps[128][68]
#define QS_OFF 0
#define KT_OFF (128*68)
#define VS_OFF (KT_OFF + 64*68)
#define PS_OFF (VS_OFF + 64*72)
#define ATTN_SMEM ((PS_OFF + 128*68)*4)

__global__ void __launch_bounds__(128) attn_mma(const float* __restrict__ Q,
                         const float* __restrict__ K,
                         const float* __restrict__ V,
                         float* __restrict__ O) {
    extern __shared__ float sm[];
    float* Qs = sm + QS_OFF;
    float* Kt = sm + KT_OFF;
    float* Vs = sm + VS_OFF;
    float* Ps = sm + PS_OFF;

    int tid  = threadIdx.x;
    int warp = tid >> 5, lane = tid & 31;
    int group = lane >> 2, tig = lane & 3;
    int q0 = blockIdx.x * 128;
    int h  = blockIdx.y, b = blockIdx.z;
    const size_t base = ((size_t)b * LL) * DIMC + (size_t)h * HDIM;

    // load Q tile, fold SCALE (exact pow2, preserves tf32 rounding)
#pragma unroll
    for (int i = 0; i < 16; i++) {
        int p = tid + 128*i;
        int r = p >> 4, c4 = (p & 15) * 4;
        float4 q4 = *(const float4*)&Q[base + (size_t)(q0+r)*256 + c4];
        float* dst = &Qs[r*68 + c4];
        dst[0] = q4.x*SCALE_F; dst[1] = q4.y*SCALE_F;
        dst[2] = q4.z*SCALE_F; dst[3] = q4.w*SCALE_F;
    }
    __syncthreads();

    float mst[2][2], lst[2][2];
#pragma unroll
    for (int mi = 0; mi < 2; mi++) { mst[mi][0]=mst[mi][1]=-1e30f; lst[mi][0]=lst[mi][1]=0.f; }
    float o[2][8][4];
#pragma unroll
    for (int mi = 0; mi < 2; mi++)
#pragma unroll
        for (int nj = 0; nj < 8; nj++)
#pragma unroll
            for (int c = 0; c < 4; c++) o[mi][nj][c] = 0.f;

    int rbase = warp*32 + group;

    for (int kt = 0; kt < LL; kt += 64) {
#pragma unroll
        for (int i = 0; i < 8; i++) {
            int p = tid + 128*i;
            int r = p >> 4, c4 = (p & 15) * 4;
            *(float4*)&Kt[r*68 + c4] = *(const float4*)&K[base + (size_t)(kt+r)*256 + c4];
            *(float4*)&Vs[r*72 + c4] = *(const float4*)&V[base + (size_t)(kt+r)*256 + c4];
        }
        __syncthreads();

        // S = (Q*scale) Kt
        float s[2][8][4];
#pragma unroll
        for (int mi = 0; mi < 2; mi++)
#pragma unroll
            for (int nj = 0; nj < 8; nj++)
#pragma unroll
                for (int c = 0; c < 4; c++) s[mi][nj][c] = 0.f;
#pragma unroll
        for (int ks = 0; ks < 8; ks++) {
            unsigned a[2][4];
#pragma unroll
            for (int mi = 0; mi < 2; mi++) {
                const float* qp = &Qs[(rbase + mi*16)*68 + ks*8];
                a[mi][0] = __float_as_uint(qp[tig]);
                a[mi][1] = __float_as_uint(qp[8*68 + tig]);
                a[mi][2] = __float_as_uint(qp[tig+4]);
                a[mi][3] = __float_as_uint(qp[8*68 + tig+4]);
            }
#pragma unroll
            for (int nj = 0; nj < 8; nj++) {
                const float* kp = &Kt[(nj*8+group)*68 + ks*8];
                unsigned b0 = __float_as_uint(kp[tig]);
                unsigned b1 = __float_as_uint(kp[tig+4]);
                mma8(s[0][nj], a[0][0],a[0][1],a[0][2],a[0][3], b0,b1);
                mma8(s[1][nj], a[1][0],a[1][1],a[1][2],a[1][3], b0,b1);
            }
        }

        // online softmax: 4 rows/thread, quad-shuffle reductions
#pragma unroll
        for (int mi = 0; mi < 2; mi++)
#pragma unroll
            for (int hf = 0; hf < 2; hf++) {
                float mx = -1e30f;
#pragma unroll
                for (int nj = 0; nj < 8; nj++)
                    mx = fmaxf(mx, fmaxf(s[mi][nj][2*hf], s[mi][nj][2*hf+1]));
                mx = fmaxf(mx, __shfl_xor_sync(0xffffffffu, mx, 1));
                mx = fmaxf(mx, __shfl_xor_sync(0xffffffffu, mx, 2));
                float mn = fmaxf(mst[mi][hf], mx);
                float sum = 0.f;
#pragma unroll
                for (int nj = 0; nj < 8; nj++) {
                    float e0 = __expf(s[mi][nj][2*hf]   - mn);
                    float e1 = __expf(s[mi][nj][2*hf+1] - mn);
                    s[mi][nj][2*hf] = e0; s[mi][nj][2*hf+1] = e1;
                    sum += e0 + e1;
                }
                sum += __shfl_xor_sync(0xffffffffu, sum, 1);
                sum += __shfl_xor_sync(0xffffffffu, sum, 2);
                float alpha = __expf(mst[mi][hf] - mn);
                lst[mi][hf] = lst[mi][hf]*alpha + sum;
                mst[mi][hf] = mn;
#pragma unroll
                for (int nj = 0; nj < 8; nj++) {
                    o[mi][nj][2*hf]   *= alpha;
                    o[mi][nj][2*hf+1] *= alpha;
                }
            }

        // store P (warp-private rows) tf32-rounded
#pragma unroll
        for (int mi = 0; mi < 2; mi++) {
            int r0 = rbase + mi*16;
#pragma unroll
            for (int nj = 0; nj < 8; nj++) {
                int c = nj*8 + 2*tig;
                *(float2*)&Ps[r0*68 + c]     = make_float2(to_tf32(s[mi][nj][0]), to_tf32(s[mi][nj][1]));
                *(float2*)&Ps[(r0+8)*68 + c] = make_float2(to_tf32(s[mi][nj][2]), to_tf32(s[mi][nj][3]));
            }
        }
        __syncwarp();

        // O += P V
#pragma unroll
        for (int ks = 0; ks < 8; ks++) {
            unsigned a[2][4];
#pragma unroll
            for (int mi = 0; mi < 2; mi++) {
                const float* pp = &Ps[(rbase + mi*16)*68 + ks*8];
                a[mi][0] = __float_as_uint(pp[tig]);
                a[mi][1] = __float_as_uint(pp[8*68 + tig]);
                a[mi][2] = __float_as_uint(pp[tig+4]);
                a[mi][3] = __float_as_uint(pp[8*68 + tig+4]);
            }
#pragma unroll
            for (int nj = 0; nj < 8; nj++) {
                unsigned b0 = __float_as_uint(Vs[(ks*8+tig)*72 + nj*8+group]);
                unsigned b1 = __float_as_uint(Vs[(ks*8+tig+4)*72 + nj*8+group]);
                mma8(o[0][nj], a[0][0],a[0][1],a[0][2],a[0][3], b0,b1);
                mma8(o[1][nj], a[1][0],a[1][1],a[1][2],a[1][3], b0,b1);
            }
        }
        __syncthreads();      // before next tile overwrites Kt/Vs
    }

#pragma unroll
    for (int mi = 0; mi < 2; mi++)
#pragma unroll
        for (int hf = 0; hf < 2; hf++) {
            float inv = 1.f / lst[mi][hf];
            size_t r = q0 + rbase + mi*16 + hf*8;
#pragma unroll
            for (int nj = 0; nj < 8; nj++) {
                int c = nj*8 + 2*tig;
                *(float2*)&O[base + r*256 + c] =
                    make_float2(to_tf32(o[mi][nj][2*hf]*inv), to_tf32(o[mi][nj][2*hf+1]*inv));
            }
        }
}

// ---------------- 4) output projection (tf32 mma) + fused LayerNorm ----------------
// BM=32, BN=256; 256 threads; warp grid 2(m)x4(n); warp tile 16x64; grid 192
__global__ void gemm_p_ln(const float* __restrict__ A, const float* __restrict__ W,
                          const float* __restrict__ bias, const float* __restrict__ gamma,
                          const float* __restrict__ beta, float* __restrict__ Out) {
    __shared__ float As[32][36];
    __shared__ float Ws[256][36];
    __shared__ float psum[32][4];
    __shared__ float psq[32][4];
    int tid = threadIdx.x;
    int warp = tid >> 5, lane = tid & 31;
    int group = lane >> 2, tig = lane & 3;
    int wm = warp >> 2, wn = warp & 3;
    int m0 = blockIdx.x * 32;

    float acc[8][4];
#pragma unroll
    for (int nj = 0; nj < 8; nj++)
#pragma unroll
        for (int c = 0; c < 4; c++) acc[nj][c] = 0.f;

    for (int kk = 0; kk < 256; kk += 32) {
        {
            int r = tid >> 3, c4 = (tid & 7) * 4;
            float4 a4 = *(const float4*)&A[(size_t)(m0+r)*256 + kk + c4];
            As[r][c4+0]=a4.x; As[r][c4+1]=a4.y; As[r][c4+2]=a4.z; As[r][c4+3]=a4.w;
        }
#pragma unroll
        for (int i = 0; i < 8; i++) {
            int p = tid + 256*i;
            int r = p >> 3, c4 = (p & 7) * 4;
            float4 w4 = *(const float4*)&W[(size_t)r*256 + kk + c4];
            Ws[r][c4+0]=to_tf32(w4.x); Ws[r][c4+1]=to_tf32(w4.y);
            Ws[r][c4+2]=to_tf32(w4.z); Ws[r][c4+3]=to_tf32(w4.w);
        }
        __syncthreads();
#pragma unroll
        for (int ks = 0; ks < 4; ks++) {
            unsigned a0,a1,a2,a3;
            int mr = wm*16 + group;
            a0 = __float_as_uint(As[mr  ][ks*8+tig  ]);
            a1 = __float_as_uint(As[mr+8][ks*8+tig  ]);
            a2 = __float_as_uint(As[mr  ][ks*8+tig+4]);
            a3 = __float_as_uint(As[mr+8][ks*8+tig+4]);
#pragma unroll
            for (int nj = 0; nj < 8; nj++) {
                int nr = wn*64 + nj*8 + group;
                unsigned b0 = __float_as_uint(Ws[nr][ks*8+tig  ]);
                unsigned b1 = __float_as_uint(Ws[nr][ks*8+tig+4]);
                mma8(acc[nj], a0,a1,a2,a3, b0,b1);
            }
        }
        __syncthreads();
    }

    // bias + per-row partial stats over this warp's 64 columns
    float rs[2] = {0.f, 0.f}, rq[2] = {0.f, 0.f};
#pragma unroll
    for (int nj = 0; nj < 8; nj++) {
        int c = wn*64 + nj*8 + 2*tig;
        float b0v = bias[c], b1v = bias[c+1];
        acc[nj][0] += b0v; acc[nj][1] += b1v;
        acc[nj][2] += b0v; acc[nj][3] += b1v;
        rs[0] += acc[nj][0] + acc[nj][1];
        rq[0] += acc[nj][0]*acc[nj][0] + acc[nj][1]*acc[nj][1];
        rs[1] += acc[nj][2] + acc[nj][3];
        rq[1] += acc[nj][2]*acc[nj][2] + acc[nj][3]*acc[nj][3];
    }
#pragma unroll
    for (int hf = 0; hf < 2; hf++) {
        rs[hf] += __shfl_xor_sync(0xffffffffu, rs[hf], 1);
        rs[hf] += __shfl_xor_sync(0xffffffffu, rs[hf], 2);
        rq[hf] += __shfl_xor_sync(0xffffffffu, rq[hf], 1);
        rq[hf] += __shfl_xor_sync(0xffffffffu, rq[hf], 2);
    }
    if (tig == 0) {
        int lr = wm*16 + group;
        psum[lr][wn]   = rs[0];  psq[lr][wn]   = rq[0];
        psum[lr+8][wn] = rs[1];  psq[lr+8][wn] = rq[1];
    }
    __syncthreads();
#pragma unroll
    for (int hf = 0; hf < 2; hf++) {
        int lr = wm*16 + group + hf*8;
        float S   = psum[lr][0] + psum[lr][1] + psum[lr][2] + psum[lr][3];
        float Qs2 = psq[lr][0]  + psq[lr][1]  + psq[lr][2]  + psq[lr][3];
        float mu  = S * (1.f/256.f);
        float var = Qs2 * (1.f/256.f) - mu*mu;
        float rstd = rsqrtf(var + LNEPS);
        size_t r = m0 + lr;
#pragma unroll
        for (int nj = 0; nj < 8; nj++) {
            int c = wn*64 + nj*8 + 2*tig;
            float v0 = acc[nj][hf*2+0], v1 = acc[nj][hf*2+1];
            *(float2*)&Out[r*256 + c] = make_float2((v0-mu)*rstd*gamma[c]   + beta[c],
                                                    (v1-mu)*rstd*gamma[c+1] + beta[c+1]);
        }
    }
}

// ---------------- 5) mean over views + transpose to [B, C, H, W] ----------------
__global__ void mean_views(float* __restrict__ out) {
    __shared__ float tile[32][33];
    int b  = blockIdx.z;
    int n0 = blockIdx.x * 32, c0 = blockIdx.y * 32;
    int tx = threadIdx.x, ty = threadIdx.y;
    float s = 0.f;
#pragma unroll
    for (int v = 0; v < VV; v++)
        s += g_p[((size_t)(b*LL + v*NN + n0 + ty))*DIMC + c0 + tx];
    tile[ty][tx] = s * (1.0f/3.0f);
    __syncthreads();
    out[((size_t)(b*DIMC + c0 + ty))*NN + n0 + tx] = tile[tx][ty];
}

// ---------------- launch ----------------
extern "C" void kernel_launch(void* const* d_in, const int* in_sizes, int n_in,
                              void* d_out, int out_size) {
    const float* f     = (const float*)d_in[0];
    const float* Wq    = (const float*)d_in[1];
    const float* bq    = (const float*)d_in[2];
    const float* Wk    = (const float*)d_in[3];
    const float* bk    = (const float*)d_in[4];
    const float* Wv    = (const float*)d_in[5];
    const float* bv    = (const float*)d_in[6];
    const float* Wp    = (const float*)d_in[7];
    const float* bp    = (const float*)d_in[8];
    const float* gamma = (const float*)d_in[9];
    const float* beta  = (const float*)d_in[10];
    float* out = (float*)d_out;

    float *px, *pq, *pk, *pv, *po, *pp;
    cudaGetSymbolAddress((void**)&px, g_x);
    cudaGetSymbolAddress((void**)&pq, g_q);
    cudaGetSymbolAddress((void**)&pk, g_k);
    cudaGetSymbolAddress((void**)&pv, g_v);
    cudaGetSymbolAddress((void**)&po, g_o);
    cudaGetSymbolAddress((void**)&pp, g_p);

    static int smem_set = 0;
    if (!smem_set) {
        cudaFuncSetAttribute(attn_mma, cudaFuncAttributeMaxDynamicSharedMemorySize, ATTN_SMEM);
        smem_set = 1;
    }

    pack_x<<<dim3(NN/32, DIMC/32, VV*BB), dim3(32,32)>>>(f);
    gemm_qkv<<<dim3(MROWS/64, 2, 3), 256>>>(px, Wq, bq, Wk, bk, Wv, bv);
    attn_mma<<<dim3(LL/128, NHEAD, BB), 128, ATTN_SMEM>>>(pq, pk, pv, po);
    gemm_p_ln<<<MROWS/32, 256>>>(po, Wp, bp, gamma, beta, pp);
    mean_views<<<dim3(NN/32, DIMC/32, BB), dim3(32,32)>>>(out);
}